// round 16
// baseline (speedup 1.0000x reference)
#include <cuda_runtime.h>
#include <cuda_bf16.h>
#include <cuda_fp16.h>
#include <cstdint>

// ---------------- problem constants ----------------
#define NN 50000
#define EE 500000
#define GG 64

// ---------------- scratch (device globals; no allocation allowed) ----------
__device__ __half g_t1[(size_t)EE * 256];     // UV node buffer fp16 (<= 50K x 512)
__device__ __half g_t2[(size_t)EE * 256];     // edge intermediate t2 (fp16, permuted)
__device__ float g_hA[(size_t)NN * 256];
__device__ float g_hB[(size_t)NN * 256];
__device__ float g_stats[1024];
__device__ float g_norm[1024];
__device__ float g_bias2[512];
__device__ int   g_deg[NN];
__device__ int   g_rowptr[NN + 1];
__device__ int   g_cursor[NN];
__device__ int   g_psrc[EE];
__device__ int   g_pdst[EE];
__device__ int   g_cnt[GG];
__device__ int   g_gstart[GG + 1];
__device__ float g_pool[GG * 256];
__device__ float g_zbuf[GG * 128];
__device__ __nv_bfloat16 g_wth[172032];
__device__ __nv_bfloat16 g_wtl[172032];

// ---------------- mma.sync / ldmatrix helpers ------------------------------
#define MMA_BF16(d, a, b)                                                        \
    asm volatile("mma.sync.aligned.m16n8k16.row.col.f32.bf16.bf16.f32 "          \
                 "{%0,%1,%2,%3}, {%4,%5,%6,%7}, {%8,%9}, {%0,%1,%2,%3};"         \
                 : "+f"((d)[0]), "+f"((d)[1]), "+f"((d)[2]), "+f"((d)[3])        \
                 : "r"((a)[0]), "r"((a)[1]), "r"((a)[2]), "r"((a)[3]),           \
                   "r"((b)[0]), "r"((b)[1]))

#define LDSM_X4(r0, r1, r2, r3, addr)                                            \
    asm volatile("ldmatrix.sync.aligned.m8n8.x4.shared.b16 {%0,%1,%2,%3}, [%4];" \
                 : "=r"(r0), "=r"(r1), "=r"(r2), "=r"(r3) : "r"(addr))

__device__ __forceinline__ uint32_t smem_u32(const void* p) {
    uint32_t a;
    asm("{ .reg .u64 t; cvta.to.shared.u64 t, %1; cvt.u32.u64 %0, t; }" : "=r"(a) : "l"(p));
    return a;
}

// ---------------- small utility kernels ----------------
__global__ void hist_deg_kernel(const int* __restrict__ dst, int* __restrict__ deg, int E) {
    int e = blockIdx.x * blockDim.x + threadIdx.x;
    if (e < E) atomicAdd(&deg[dst[e]], 1);
}
__global__ void hist_cnt_kernel(const int* __restrict__ batch, int* __restrict__ cnt, int n) {
    int i = blockIdx.x * blockDim.x + threadIdx.x;
    if (i < n) atomicAdd(&cnt[batch[i]], 1);
}
__global__ void scan_kernel(const int* __restrict__ deg, int* __restrict__ rowptr,
                            int* __restrict__ cursor, const int* __restrict__ cnt,
                            int* __restrict__ gstart, int n) {
    __shared__ int sh[1024];
    __shared__ int carry;
    int t = threadIdx.x;
    if (t == 0) carry = 0;
    __syncthreads();
    for (int base = 0; base < n; base += 1024) {
        int idx = base + t;
        int v = (idx < n) ? deg[idx] : 0;
        sh[t] = v;
        __syncthreads();
        for (int off = 1; off < 1024; off <<= 1) {
            int add = (t >= off) ? sh[t - off] : 0;
            __syncthreads();
            sh[t] += add;
            __syncthreads();
        }
        int ex = sh[t] - v;
        int cbase = carry;
        if (idx < n) { rowptr[idx] = cbase + ex; cursor[idx] = cbase + ex; }
        __syncthreads();
        if (t == 1023) carry = cbase + sh[1023];
        __syncthreads();
    }
    if (t == 0) {
        rowptr[n] = carry;
        int s = 0;
        for (int g = 0; g < GG; g++) { gstart[g] = s; s += cnt[g]; }
        gstart[GG] = s;
    }
}
__global__ void fill_csr_kernel(const int* __restrict__ src, const int* __restrict__ dst,
                                int* __restrict__ cursor,
                                int* __restrict__ psrc, int* __restrict__ pdst, int E) {
    int e = blockIdx.x * blockDim.x + threadIdx.x;
    if (e < E) {
        int d = dst[e];
        int p = atomicAdd(&cursor[d], 1);
        psrc[p] = src[e];
        pdst[p] = d;
    }
}

__global__ void convert_w_kernel(const float* __restrict__ W,
                                 __nv_bfloat16* __restrict__ Wth,
                                 __nv_bfloat16* __restrict__ Wtl,
                                 int K, int OC, int KPAD) {
    int idx = blockIdx.x * blockDim.x + threadIdx.x;
    if (idx >= OC * KPAD) return;
    int n = idx / KPAD, k = idx % KPAD;
    float w = (k < K) ? W[(size_t)k * OC + n] : 0.f;
    __nv_bfloat16 h = __float2bfloat16_rn(w);
    Wth[idx] = h;
    Wtl[idx] = __float2bfloat16_rn(w - __bfloat162float(h));
}

__global__ void convert_wsplit_kernel(const float* __restrict__ W1,
                                      __nv_bfloat16* __restrict__ Wth,
                                      __nv_bfloat16* __restrict__ Wtl,
                                      int C, int OC, int KPAD) {
    int idx = blockIdx.x * blockDim.x + threadIdx.x;
    if (idx >= 2 * OC * KPAD) return;
    int n = idx / KPAD, k = idx % KPAD;
    float w = 0.f;
    if (k < C) {
        if (n < OC) w = W1[(size_t)k * OC + n] - W1[(size_t)(k + C) * OC + n];
        else        w = W1[(size_t)(k + C) * OC + (n - OC)];
    }
    __nv_bfloat16 h = __float2bfloat16_rn(w);
    Wth[idx] = h;
    Wtl[idx] = __float2bfloat16_rn(w - __bfloat162float(h));
}

// ---------------- tensor-core GEMM (double-buffered, 1 sync/chunk) ---------
// Block tile BM x BN; warps = (BM/32) x (BN/32); warp tile 32x32 (acc 32 regs).
// 3 MMAs per k16 (hi/lo split).  Dynamic smem.  ALL outputs fp16.
// MODE 0: node GEMM, A row i = fA(f32)[i*K..].  Rows = N.
// MODE 1: edge GEMM over permuted edges, A row p =
//         relu((U[pdst]+V[psrc])*an+cn), U/V fp16; exact fp32 stats.
template <int K, int OC, int BM, int BN, int MODE, bool STATS>
__global__ __launch_bounds__(BM * BN / 32, 512 * 32 / (BM * BN))
void mgemm_kernel(const void* __restrict__ fA_v,
                  const int* __restrict__ src, const int* __restrict__ dst,
                  const float* __restrict__ an, const float* __restrict__ cn,
                  const __nv_bfloat16* __restrict__ Wth,
                  const __nv_bfloat16* __restrict__ Wtl,
                  const float* __restrict__ bias,
                  __half* __restrict__ out,
                  float* __restrict__ stat_sum, float* __restrict__ stat_sq,
                  int Rows) {
    constexpr int THREADS = BM * BN / 32;
    constexpr int MW = BM / 32;
    constexpr int KPAD = (K + 31) / 32 * 32;
    constexpr int NCH = KPAD / 32;
    constexpr int SAS = 40;
    constexpr int ASTR = (MODE == 1) ? 2 * K : K;
    constexpr int TPR = THREADS / BM;
    constexpr int UNITS = 8 / TPR;
    constexpr int NB_LD = 128 / BM;
    constexpr int EST = BN + 8;
    constexpr int NPASS = BM / 64;

    constexpr int ABUF = BM * SAS * 2;
    constexpr int BBUF = BN * SAS * 2;
    constexpr int OFF_AH = 0;
    constexpr int OFF_AL = 2 * ABUF;
    constexpr int OFF_BH = 4 * ABUF;
    constexpr int OFF_BL = 4 * ABUF + 2 * BBUF;
    constexpr int OFF_DST = 4 * ABUF + 4 * BBUF;
    constexpr int OFF_SRC = OFF_DST + 512;
    constexpr int OFF_AN = OFF_SRC + 512;
    constexpr int OFF_CN = OFF_AN + KPAD * 4;
    constexpr int OFF_SSUM = 64 * EST * 4;
    constexpr int OFF_SSQ = OFF_SSUM + BN * 4;

    extern __shared__ char SM[];
    int* sdst = reinterpret_cast<int*>(SM + OFF_DST);
    int* ssrc = reinterpret_cast<int*>(SM + OFF_SRC);
    float* sAn = reinterpret_cast<float*>(SM + OFF_AN);
    float* sCn = reinterpret_cast<float*>(SM + OFF_CN);

    const int tid = threadIdx.x;
    const int lane = tid & 31;
    const int wid = tid >> 5;
    const int wm = wid % MW;
    const int wn = wid / MW;
    const int e0 = blockIdx.x * BM;
    const int col0 = blockIdx.y * BN;

    const uint32_t sAh_u = smem_u32(SM + OFF_AH);
    const uint32_t sAl_u = smem_u32(SM + OFF_AL);
    const uint32_t sBh_u = smem_u32(SM + OFF_BH);
    const uint32_t sBl_u = smem_u32(SM + OFF_BL);

    if (MODE == 1) {
        if (tid < BM) {
            int e = e0 + tid;
            int ee = (e < Rows) ? e : (Rows - 1);
            sdst[tid] = dst[ee];
            ssrc[tid] = src[ee];
        }
        for (int i = tid; i < K; i += THREADS) { sAn[i] = an[i]; sCn[i] = cn[i]; }
    }
    __syncthreads();

    float acc[2][4][4];
#pragma unroll
    for (int mt = 0; mt < 2; mt++)
#pragma unroll
        for (int nt = 0; nt < 4; nt++)
#pragma unroll
            for (int j = 0; j < 4; j++) acc[mt][nt][j] = 0.f;

    const int arow = tid / TPR;
    const int acg = (tid % TPR) * (32 / TPR);
    int nd = 0, ns = 0;
    if (MODE == 1) { nd = sdst[arow]; ns = ssrc[arow]; }

    const int bn0 = tid >> 2;
    const int bu_ = tid & 3;

    float4 P[UNITS], Q[UNITS];
    uint4 BHr[NB_LD], BLr[NB_LD];

    auto load_chunk = [&](int ch) {
        const int k0 = ch * 32 + acg;
        if (MODE == 1) {
            const __half* UVh = reinterpret_cast<const __half*>(fA_v);
            const __half2* Ur = reinterpret_cast<const __half2*>(UVh + (size_t)nd * ASTR + k0);
            const __half2* Vr = reinterpret_cast<const __half2*>(UVh + (size_t)ns * ASTR + K + k0);
#pragma unroll
            for (int u = 0; u < UNITS; u++) {
                float2 p0 = __half22float2(Ur[u * 2]);
                float2 p1 = __half22float2(Ur[u * 2 + 1]);
                float2 q0 = __half22float2(Vr[u * 2]);
                float2 q1 = __half22float2(Vr[u * 2 + 1]);
                P[u] = make_float4(p0.x, p0.y, p1.x, p1.y);
                Q[u] = make_float4(q0.x, q0.y, q1.x, q1.y);
            }
        } else {
            const float* fA = reinterpret_cast<const float*>(fA_v);
            const int i = e0 + arow;
            if (K % 4 == 0) {
                if (i < Rows) {
#pragma unroll
                    for (int u = 0; u < UNITS; u++)
                        P[u] = *reinterpret_cast<const float4*>(&fA[(size_t)i * K + k0 + u * 4]);
                } else {
#pragma unroll
                    for (int u = 0; u < UNITS; u++) P[u] = make_float4(0.f, 0.f, 0.f, 0.f);
                }
            } else {  // K=7 scalar path (NCH==1)
#pragma unroll
                for (int u = 0; u < UNITS; u++) {
                    float t[4];
#pragma unroll
                    for (int j = 0; j < 4; j++) {
                        int kk = k0 + u * 4 + j;
                        t[j] = (i < Rows && kk < K) ? fA[(size_t)i * K + kk] : 0.f;
                    }
                    P[u] = make_float4(t[0], t[1], t[2], t[3]);
                }
            }
        }
    };
    auto load_B = [&](int ch) {
#pragma unroll
        for (int l = 0; l < NB_LD; l++) {
            int r = bn0 + l * (THREADS / 4);
            size_t soff = (size_t)(col0 + r) * KPAD + ch * 32 + bu_ * 8;
            BHr[l] = *reinterpret_cast<const uint4*>(Wth + soff);
            BLr[l] = *reinterpret_cast<const uint4*>(Wtl + soff);
        }
    };
    auto store_chunk = [&](int ch, int buf) {
        char* aH = SM + OFF_AH + buf * ABUF;
        char* aL = SM + OFF_AL + buf * ABUF;
        const int k0 = ch * 32 + acg;
#pragma unroll
        for (int u = 0; u < UNITS; u++) {
            float4 v;
            if (MODE == 1) {
                const int k = k0 + u * 4;
                v.x = fmaxf((P[u].x + Q[u].x) * sAn[k + 0] + sCn[k + 0], 0.f);
                v.y = fmaxf((P[u].y + Q[u].y) * sAn[k + 1] + sCn[k + 1], 0.f);
                v.z = fmaxf((P[u].z + Q[u].z) * sAn[k + 2] + sCn[k + 2], 0.f);
                v.w = fmaxf((P[u].w + Q[u].w) * sAn[k + 3] + sCn[k + 3], 0.f);
            } else {
                v = P[u];
            }
            __nv_bfloat162 h01 = __float22bfloat162_rn(make_float2(v.x, v.y));
            __nv_bfloat162 h23 = __float22bfloat162_rn(make_float2(v.z, v.w));
            float2 hf01 = __bfloat1622float2(h01);
            float2 hf23 = __bfloat1622float2(h23);
            __nv_bfloat162 l01 = __float22bfloat162_rn(make_float2(v.x - hf01.x, v.y - hf01.y));
            __nv_bfloat162 l23 = __float22bfloat162_rn(make_float2(v.z - hf23.x, v.w - hf23.y));
            uint2 H, L;
            H.x = *reinterpret_cast<uint32_t*>(&h01);
            H.y = *reinterpret_cast<uint32_t*>(&h23);
            L.x = *reinterpret_cast<uint32_t*>(&l01);
            L.y = *reinterpret_cast<uint32_t*>(&l23);
            int so = (arow * SAS + acg + u * 4) * 2;
            *reinterpret_cast<uint2*>(aH + so) = H;
            *reinterpret_cast<uint2*>(aL + so) = L;
        }
#pragma unroll
        for (int l = 0; l < NB_LD; l++) {
            int r = bn0 + l * (THREADS / 4);
            int doff = (r * SAS + bu_ * 8) * 2;
            *reinterpret_cast<uint4*>(SM + OFF_BH + buf * BBUF + doff) = BHr[l];
            *reinterpret_cast<uint4*>(SM + OFF_BL + buf * BBUF + doff) = BLr[l];
        }
    };

    const int a_lrow = (lane & 7) + ((lane >> 3) & 1) * 8;
    const int a_lcol = (lane >> 4) * 8;
    const int b_lrow = (lane & 7) + (lane >> 4) * 8;
    const int b_lcol = ((lane >> 3) & 1) * 8;

    load_chunk(0);
    load_B(0);
    store_chunk(0, 0);
    __syncthreads();

    for (int ch = 0; ch < NCH; ch++) {
        const int cur = ch & 1;
        if (ch + 1 < NCH) { load_chunk(ch + 1); load_B(ch + 1); }

        const uint32_t aHb = sAh_u + cur * ABUF;
        const uint32_t aLb = sAl_u + cur * ABUF;
        const uint32_t bHb = sBh_u + cur * BBUF;
        const uint32_t bLb = sBl_u + cur * BBUF;
#pragma unroll
        for (int ks = 0; ks < 2; ks++) {
            const int kb = ks * 16;
            uint32_t ah[2][4], al[2][4];
#pragma unroll
            for (int mt = 0; mt < 2; mt++) {
                int r = wm * 32 + mt * 16 + a_lrow;
                uint32_t off = (uint32_t)(r * SAS + kb + a_lcol) * 2;
                LDSM_X4(ah[mt][0], ah[mt][1], ah[mt][2], ah[mt][3], aHb + off);
                LDSM_X4(al[mt][0], al[mt][1], al[mt][2], al[mt][3], aLb + off);
            }
#pragma unroll
            for (int p = 0; p < 2; p++) {
                int n0 = wn * 32 + p * 16;
                uint32_t boff = (uint32_t)((n0 + b_lrow) * SAS + kb + b_lcol) * 2;
                uint32_t bh[4], bl[4];
                LDSM_X4(bh[0], bh[1], bh[2], bh[3], bHb + boff);
                LDSM_X4(bl[0], bl[1], bl[2], bl[3], bLb + boff);
#pragma unroll
                for (int mt = 0; mt < 2; mt++) {
                    MMA_BF16(acc[mt][2 * p], ah[mt], (&bh[0]));
                    MMA_BF16(acc[mt][2 * p], ah[mt], (&bl[0]));
                    MMA_BF16(acc[mt][2 * p], al[mt], (&bh[0]));
                    MMA_BF16(acc[mt][2 * p + 1], ah[mt], (&bh[2]));
                    MMA_BF16(acc[mt][2 * p + 1], ah[mt], (&bl[2]));
                    MMA_BF16(acc[mt][2 * p + 1], al[mt], (&bh[2]));
                }
            }
        }
        if (ch + 1 < NCH) store_chunk(ch + 1, 1 - cur);
        __syncthreads();
    }

    // ---- epilogue ----
    float* ssum = reinterpret_cast<float*>(SM + OFF_SSUM);
    float* ssq = reinterpret_cast<float*>(SM + OFF_SSQ);

    const int q = lane >> 2, s = lane & 3;

#pragma unroll
    for (int nt = 0; nt < 4; nt++) {
        const int col = col0 + wn * 32 + nt * 8 + s * 2;
        const float b0 = bias[col], b1 = bias[col + 1];
#pragma unroll
        for (int mt = 0; mt < 2; mt++) {
            acc[mt][nt][0] += b0; acc[mt][nt][1] += b1;
            acc[mt][nt][2] += b0; acc[mt][nt][3] += b1;
        }
    }

    if (STATS) {   // exact fp32 stats from accumulators (before fp16 rounding)
        for (int i = tid; i < 2 * BN; i += THREADS)
            reinterpret_cast<float*>(SM + OFF_SSUM)[i] = 0.f;
        __syncthreads();
#pragma unroll
        for (int nt = 0; nt < 4; nt++) {
            const int colw = wn * 32 + nt * 8 + s * 2;
            float s0 = 0.f, q0 = 0.f, s1 = 0.f, q1 = 0.f;
#pragma unroll
            for (int mt = 0; mt < 2; mt++) {
                const int r = wm * 32 + mt * 16 + q;
                if (e0 + r < Rows) {
                    s0 += acc[mt][nt][0]; q0 += acc[mt][nt][0] * acc[mt][nt][0];
                    s1 += acc[mt][nt][1]; q1 += acc[mt][nt][1] * acc[mt][nt][1];
                }
                if (e0 + r + 8 < Rows) {
                    s0 += acc[mt][nt][2]; q0 += acc[mt][nt][2] * acc[mt][nt][2];
                    s1 += acc[mt][nt][3]; q1 += acc[mt][nt][3] * acc[mt][nt][3];
                }
            }
#pragma unroll
            for (int m = 4; m <= 16; m <<= 1) {
                s0 += __shfl_xor_sync(0xffffffff, s0, m);
                q0 += __shfl_xor_sync(0xffffffff, q0, m);
                s1 += __shfl_xor_sync(0xffffffff, s1, m);
                q1 += __shfl_xor_sync(0xffffffff, q1, m);
            }
            if (q == 0) {
                atomicAdd(&ssum[colw], s0);
                atomicAdd(&ssq[colw], q0);
                atomicAdd(&ssum[colw + 1], s1);
                atomicAdd(&ssq[colw + 1], q1);
            }
        }
        __syncthreads();
        if (tid < BN) {
            atomicAdd(&stat_sum[col0 + tid], ssum[tid]);
            atomicAdd(&stat_sq[col0 + tid], ssq[tid]);
        }
    }

    // coalesced smem-staged fp16 store (NPASS 64-row passes)
    {
        __half* ebuf = reinterpret_cast<__half*>(SM);
#pragma unroll
        for (int pass = 0; pass < NPASS; pass++) {
            __syncthreads();
            if (NPASS == 1 || (wm >> 1) == pass) {
                const int wml = wm & 1;
#pragma unroll
                for (int mt = 0; mt < 2; mt++) {
                    const int rl = wml * 32 + mt * 16 + q;
#pragma unroll
                    for (int nt = 0; nt < 4; nt++) {
                        const int colw = wn * 32 + nt * 8 + s * 2;
                        __half2 v01 = __float22half2_rn(
                            make_float2(acc[mt][nt][0], acc[mt][nt][1]));
                        __half2 v23 = __float22half2_rn(
                            make_float2(acc[mt][nt][2], acc[mt][nt][3]));
                        *reinterpret_cast<__half2*>(&ebuf[rl * EST + colw]) = v01;
                        *reinterpret_cast<__half2*>(&ebuf[(rl + 8) * EST + colw]) = v23;
                    }
                }
            }
            __syncthreads();
            constexpr int II = 8 * BN / THREADS;
#pragma unroll
            for (int ii = 0; ii < II; ii++) {
                const int i = tid + ii * THREADS;
                const int row = i / (BN / 8), c8 = i % (BN / 8);
                const int e = e0 + pass * 64 + row;
                if (e < Rows) {
                    uint4 v = *reinterpret_cast<uint4*>(&ebuf[row * EST + c8 * 8]);
                    *reinterpret_cast<uint4*>(&out[(size_t)e * OC + col0 + c8 * 8]) = v;
                }
            }
        }
    }
}

// ---------------- node-centric edge stats (fp16 UV) ----------------
template <int OC>
__global__ __launch_bounds__(256)
void estats_kernel(const __half* __restrict__ UV, const int* __restrict__ psrc,
                   const int* __restrict__ rowptr,
                   float* __restrict__ sum, float* __restrict__ sq, int n) {
    constexpr int R = OC / 64;           // half2 pairs per lane
    __shared__ float ss[OC], sv[OC];
    const int tid = threadIdx.x, lane = tid & 31, wid = tid >> 5;
    for (int i = tid; i < OC; i += 256) { ss[i] = 0.f; sv[i] = 0.f; }
    __syncthreads();
    float2 s[R], q[R];
#pragma unroll
    for (int j = 0; j < R; j++) { s[j] = make_float2(0.f, 0.f); q[j] = make_float2(0.f, 0.f); }
    const int nwarps = gridDim.x * 8;
    for (int i = blockIdx.x * 8 + wid; i < n; i += nwarps) {
        const int beg = rowptr[i], end = rowptr[i + 1];
        const float dg = (float)(end - beg);
        float2 U[R], sV[R], sV2[R];
        const __half2* Ur = reinterpret_cast<const __half2*>(UV + (size_t)i * (2 * OC));
#pragma unroll
        for (int j = 0; j < R; j++) {
            U[j] = __half22float2(Ur[j * 32 + lane]);
            sV[j] = make_float2(0.f, 0.f);
            sV2[j] = make_float2(0.f, 0.f);
        }
        for (int p = beg; p < end; p++) {
            const __half2* Vr = reinterpret_cast<const __half2*>(
                UV + (size_t)psrc[p] * (2 * OC) + OC);
#pragma unroll
            for (int j = 0; j < R; j++) {
                float2 v = __half22float2(Vr[j * 32 + lane]);
                sV[j].x += v.x; sV[j].y += v.y;
                sV2[j].x += v.x * v.x; sV2[j].y += v.y * v.y;
            }
        }
#pragma unroll
        for (int j = 0; j < R; j++) {
            s[j].x += dg * U[j].x + sV[j].x;
            s[j].y += dg * U[j].y + sV[j].y;
            q[j].x += dg * U[j].x * U[j].x + 2.f * U[j].x * sV[j].x + sV2[j].x;
            q[j].y += dg * U[j].y * U[j].y + 2.f * U[j].y * sV[j].y + sV2[j].y;
        }
    }
#pragma unroll
    for (int j = 0; j < R; j++) {
        int ch = j * 64 + lane * 2;
        atomicAdd(&ss[ch], s[j].x);
        atomicAdd(&ss[ch + 1], s[j].y);
        atomicAdd(&sv[ch], q[j].x);
        atomicAdd(&sv[ch + 1], q[j].y);
    }
    __syncthreads();
    for (int i = tid; i < OC; i += 256) {
        atomicAdd(&sum[i], ss[i]);
        atomicAdd(&sq[i], sv[i]);
    }
}

// ---------------- BN finalize (self-zeroing) ----------------
__global__ void finalize_kernel(float* __restrict__ sum, float* __restrict__ sq,
                                const float* __restrict__ gamma, const float* __restrict__ beta,
                                float* __restrict__ a, float* __restrict__ c,
                                int OC, float invE) {
    int i = blockIdx.x * blockDim.x + threadIdx.x;
    if (i < OC) {
        float m = sum[i] * invE;
        float var = sq[i] * invE - m * m;
        float rs = rsqrtf(var + 1e-5f);
        float ai = gamma[i] * rs;
        a[i] = ai;
        c[i] = beta[i] - m * ai;
        sum[i] = 0.f;
        sq[i] = 0.f;
    }
}

// ---------------- normalize + relu + mean-aggregate (fp16 rows) ------------
template <int OC>
__global__ __launch_bounds__(256)
void aggregate_kernel(const __half* __restrict__ t, const int* __restrict__ rowptr,
                      const float* __restrict__ a,
                      const float* __restrict__ c, float* __restrict__ hout, int n) {
    int warp = (blockIdx.x * blockDim.x + threadIdx.x) >> 5;
    int lane = threadIdx.x & 31;
    if (warp >= n) return;
    constexpr int R = OC / 64;           // half2 pairs per lane
    float2 av[R], cv[R], acc[R];
#pragma unroll
    for (int j = 0; j < R; j++) {
        int ch = j * 64 + lane * 2;
        av[j] = make_float2(a[ch], a[ch + 1]);
        cv[j] = make_float2(c[ch], c[ch + 1]);
        acc[j] = make_float2(0.f, 0.f);
    }
    int beg = rowptr[warp], end = rowptr[warp + 1];
    for (int p = beg; p < end; p++) {
        const __half2* rowp =
            reinterpret_cast<const __half2*>(t + (size_t)p * OC);
#pragma unroll
        for (int j = 0; j < R; j++) {
            float2 v = __half22float2(rowp[j * 32 + lane]);
            acc[j].x += fmaxf(v.x * av[j].x + cv[j].x, 0.f);
            acc[j].y += fmaxf(v.y * av[j].y + cv[j].y, 0.f);
        }
    }
    float inv = 1.f / fmaxf((float)(end - beg), 1.f);
#pragma unroll
    for (int j = 0; j < R; j++) {
        int ch = j * 64 + lane * 2;
        hout[(size_t)warp * OC + ch] = acc[j].x * inv;
        hout[(size_t)warp * OC + ch + 1] = acc[j].y * inv;
    }
}

// ---------------- global mean pool + head ----------------
__global__ void pool_kernel(const float* __restrict__ h, const int* __restrict__ gstart,
                            float* __restrict__ pool) {
    int g = blockIdx.x;
    int ch = threadIdx.x;
    int beg = gstart[g], end = gstart[g + 1];
    float s = 0.f;
    for (int nidx = beg; nidx < end; nidx++) s += h[(size_t)nidx * 256 + ch];
    pool[g * 256 + ch] = s / fmaxf((float)(end - beg), 1.f);
}
__global__ void head1_kernel(const float* __restrict__ pool, const float* __restrict__ W,
                             const float* __restrict__ b, float* __restrict__ z) {
    int g = blockIdx.x, j = threadIdx.x;
    __shared__ float sp[256];
    sp[j] = pool[g * 256 + j];
    sp[j + 128] = pool[g * 256 + j + 128];
    __syncthreads();
    float s = b[j];
#pragma unroll 8
    for (int k = 0; k < 256; k++) s += sp[k] * W[k * 128 + j];
    z[g * 128 + j] = fmaxf(s, 0.f);
}
__global__ void head2_kernel(const float* __restrict__ z, const float* __restrict__ W,
                             const float* __restrict__ b, float* __restrict__ out) {
    int t = threadIdx.x;
    int g = t >> 1, j = t & 1;
    float s = b[j];
#pragma unroll 8
    for (int k = 0; k < 128; k++) s += z[g * 128 + k] * W[k * 2 + j];
    out[g * 2 + j] = s;
}

// ---------------- launch ----------------
static inline int gemm_smem(int KPAD, int BM, int BN) {
    int prod = 4 * BM * 80 + 4 * BN * 80 + 1024 + 2 * KPAD * 4;
    int epi = 64 * (BN + 8) * 4 + 8 * BN;
    return prod > epi ? prod : epi;
}

extern "C" void kernel_launch(void* const* d_in, const int* in_sizes, int n_in,
                              void* d_out, int out_size) {
    const float* x     = (const float*)d_in[0];
    const int*   ei    = (const int*)d_in[1];
    const int*   batch = (const int*)d_in[2];

    const int E = in_sizes[1] / 2;
    const int n = in_sizes[2];
    const int* srcp = ei;
    const int* dstp = ei + E;

    const float* W[3][2];  const float* B[3][2];
    const float* Gm[3][2]; const float* Bt[3][2];
    for (int l = 0; l < 3; l++) {
        int base = 3 + l * 8;
        W[l][0]  = (const float*)d_in[base + 0];
        B[l][0]  = (const float*)d_in[base + 1];
        Gm[l][0] = (const float*)d_in[base + 2];
        Bt[l][0] = (const float*)d_in[base + 3];
        W[l][1]  = (const float*)d_in[base + 4];
        B[l][1]  = (const float*)d_in[base + 5];
        Gm[l][1] = (const float*)d_in[base + 6];
        Bt[l][1] = (const float*)d_in[base + 7];
    }
    const float* hW1 = (const float*)d_in[27];
    const float* hb1 = (const float*)d_in[28];
    const float* hW2 = (const float*)d_in[29];
    const float* hb2 = (const float*)d_in[30];

    float *hA, *hB, *stats, *norm, *pool, *zbuf, *bias2;
    __half *UV, *t2;
    int *deg, *rowptr, *cursor, *psrc, *pdst, *cnt, *gstart;
    __nv_bfloat16 *wth, *wtl;
    cudaGetSymbolAddress((void**)&UV, g_t1);
    cudaGetSymbolAddress((void**)&t2, g_t2);
    cudaGetSymbolAddress((void**)&hA, g_hA);
    cudaGetSymbolAddress((void**)&hB, g_hB);
    cudaGetSymbolAddress((void**)&stats, g_stats);
    cudaGetSymbolAddress((void**)&norm, g_norm);
    cudaGetSymbolAddress((void**)&bias2, g_bias2);
    cudaGetSymbolAddress((void**)&deg, g_deg);
    cudaGetSymbolAddress((void**)&rowptr, g_rowptr);
    cudaGetSymbolAddress((void**)&cursor, g_cursor);
    cudaGetSymbolAddress((void**)&psrc, g_psrc);
    cudaGetSymbolAddress((void**)&pdst, g_pdst);
    cudaGetSymbolAddress((void**)&cnt, g_cnt);
    cudaGetSymbolAddress((void**)&gstart, g_gstart);
    cudaGetSymbolAddress((void**)&pool, g_pool);
    cudaGetSymbolAddress((void**)&zbuf, g_zbuf);
    cudaGetSymbolAddress((void**)&wth, g_wth);
    cudaGetSymbolAddress((void**)&wtl, g_wtl);

    float* sum1 = stats + 0;   float* sq1 = stats + 256;
    float* sum2 = stats + 512; float* sq2 = stats + 768;
    float* a1 = norm + 0;   float* c1 = norm + 256;
    float* a2 = norm + 512; float* c2 = norm + 768;

    const float invE = 1.f / (float)E;
    const int EB128 = (E + 127) / 128;
    const int EB64 = (E + 63) / 64;
    const int NB = (n + 127) / 128;
    const int EG = (E + 255) / 256;
    const int NG = (n + 255) / 256;
    const int AGG = (n * 32 + 255) / 256;
    const int SGRID = 592;

    cudaFuncSetAttribute(mgemm_kernel<7, 128, 128, 128, 0, false>,   cudaFuncAttributeMaxDynamicSharedMemorySize, gemm_smem(32, 128, 128));
    cudaFuncSetAttribute(mgemm_kernel<64, 64, 128, 64, 1, true>,     cudaFuncAttributeMaxDynamicSharedMemorySize, gemm_smem(64, 128, 64));
    cudaFuncSetAttribute(mgemm_kernel<64, 256, 128, 128, 0, false>,  cudaFuncAttributeMaxDynamicSharedMemorySize, gemm_smem(64, 128, 128));
    cudaFuncSetAttribute(mgemm_kernel<128, 128, 128, 128, 1, true>,  cudaFuncAttributeMaxDynamicSharedMemorySize, gemm_smem(128, 128, 128));
    cudaFuncSetAttribute(mgemm_kernel<128, 512, 128, 128, 0, false>, cudaFuncAttributeMaxDynamicSharedMemorySize, gemm_smem(128, 128, 128));
    cudaFuncSetAttribute(mgemm_kernel<256, 256, 64, 256, 1, true>,   cudaFuncAttributeMaxDynamicSharedMemorySize, gemm_smem(256, 64, 256));

    // ---- CSR build (permuted src/dst directly) ----
    cudaMemsetAsync(deg, 0, n * sizeof(int));
    cudaMemsetAsync(cnt, 0, GG * sizeof(int));
    cudaMemsetAsync(stats, 0, 1024 * sizeof(float));
    hist_deg_kernel<<<EG, 256>>>(dstp, deg, E);
    hist_cnt_kernel<<<NG, 256>>>(batch, cnt, n);
    scan_kernel<<<1, 1024>>>(deg, rowptr, cursor, cnt, gstart, n);
    fill_csr_kernel<<<EG, 256>>>(srcp, dstp, cursor, psrc, pdst, E);

    // ---- weight conversion ----
    convert_wsplit_kernel<<<(128 * 32 + 255) / 256, 256>>>(W[0][0], wth + 0, wtl + 0, 7, 64, 32);
    convert_w_kernel<<<(64 * 64 + 255) / 256, 256>>>(W[0][1], wth + 4096, wtl + 4096, 64, 64, 64);
    convert_wsplit_kernel<<<(256 * 64 + 255) / 256, 256>>>(W[1][0], wth + 8192, wtl + 8192, 64, 128, 64);
    convert_w_kernel<<<(128 * 128 + 255) / 256, 256>>>(W[1][1], wth + 24576, wtl + 24576, 128, 128, 128);
    convert_wsplit_kernel<<<(512 * 128 + 255) / 256, 256>>>(W[2][0], wth + 40960, wtl + 40960, 128, 256, 128);
    convert_w_kernel<<<(256 * 256 + 255) / 256, 256>>>(W[2][1], wth + 106496, wtl + 106496, 256, 256, 256);

    // ==== layer 1: 7 -> 64 ====
    cudaMemsetAsync(bias2, 0, 512 * sizeof(float));
    cudaMemcpyAsync(bias2, B[0][0], 64 * sizeof(float), cudaMemcpyDeviceToDevice);
    mgemm_kernel<7, 128, 128, 128, 0, false><<<dim3(NB, 1), 512, gemm_smem(32, 128, 128)>>>(
        x, nullptr, nullptr, nullptr, nullptr, wth + 0, wtl + 0, bias2, UV, nullptr, nullptr, n);
    estats_kernel<64><<<SGRID, 256>>>(UV, psrc, rowptr, sum1, sq1, n);
    finalize_kernel<<<1, 64>>>(sum1, sq1, Gm[0][0], Bt[0][0], a1, c1, 64, invE);
    mgemm_kernel<64, 64, 128, 64, 1, true><<<dim3(EB128, 1), 256, gemm_smem(64, 128, 64)>>>(
        UV, psrc, pdst, a1, c1, wth + 4096, wtl + 4096, B[0][1], t2, sum2, sq2, E);
    finalize_kernel<<<1, 64>>>(sum2, sq2, Gm[0][1], Bt[0][1], a2, c2, 64, invE);
    aggregate_kernel<64><<<AGG, 256>>>(t2, rowptr, a2, c2, hA, n);

    // ==== layer 2: 64 -> 128 ====
    cudaMemsetAsync(bias2, 0, 512 * sizeof(float));
    cudaMemcpyAsync(bias2, B[1][0], 128 * sizeof(float), cudaMemcpyDeviceToDevice);
    mgemm_kernel<64, 256, 128, 128, 0, false><<<dim3(NB, 2), 512, gemm_smem(64, 128, 128)>>>(
        hA, nullptr, nullptr, nullptr, nullptr, wth + 8192, wtl + 8192, bias2, UV, nullptr, nullptr, n);
    estats_kernel<128><<<SGRID, 256>>>(UV, psrc, rowptr, sum1, sq1, n);
    finalize_kernel<<<1, 128>>>(sum1, sq1, Gm[1][0], Bt[1][0], a1, c1, 128, invE);
    mgemm_kernel<128, 128, 128, 128, 1, true><<<dim3(EB128, 1), 512, gemm_smem(128, 128, 128)>>>(
        UV, psrc, pdst, a1, c1, wth + 24576, wtl + 24576, B[1][1], t2, sum2, sq2, E);
    finalize_kernel<<<1, 128>>>(sum2, sq2, Gm[1][1], Bt[1][1], a2, c2, 128, invE);
    aggregate_kernel<128><<<AGG, 256>>>(t2, rowptr, a2, c2, hB, n);

    // ==== layer 3: 128 -> 256 ====
    cudaMemsetAsync(bias2, 0, 512 * sizeof(float));
    cudaMemcpyAsync(bias2, B[2][0], 256 * sizeof(float), cudaMemcpyDeviceToDevice);
    mgemm_kernel<128, 512, 128, 128, 0, false><<<dim3(NB, 4), 512, gemm_smem(128, 128, 128)>>>(
        hB, nullptr, nullptr, nullptr, nullptr, wth + 40960, wtl + 40960, bias2, UV, nullptr, nullptr, n);
    estats_kernel<256><<<SGRID, 256>>>(UV, psrc, rowptr, sum1, sq1, n);
    finalize_kernel<<<1, 256>>>(sum1, sq1, Gm[2][0], Bt[2][0], a1, c1, 256, invE);
    mgemm_kernel<256, 256, 64, 256, 1, true><<<dim3(EB64, 1), 512, gemm_smem(256, 64, 256)>>>(
        UV, psrc, pdst, a1, c1, wth + 106496, wtl + 106496, B[2][1], t2, sum2, sq2, E);
    finalize_kernel<<<1, 256>>>(sum2, sq2, Gm[2][1], Bt[2][1], a2, c2, 256, invE);
    aggregate_kernel<256><<<AGG, 256>>>(t2, rowptr, a2, c2, hA, n);

    // ---- pool + head ----
    pool_kernel<<<GG, 256>>>(hA, gstart, pool);
    head1_kernel<<<GG, 128>>>(pool, hW1, hb1, zbuf);
    head2_kernel<<<1, 128>>>(zbuf, hW2, hb2, (float*)d_out);
}

// round 17
// speedup vs baseline: 1.0648x; 1.0648x over previous
#include <cuda_runtime.h>
#include <cuda_bf16.h>
#include <cuda_fp16.h>
#include <cstdint>

// ---------------- problem constants ----------------
#define NN 50000
#define EE 500000
#define GG 64

// ---------------- scratch (device globals; no allocation allowed) ----------
__device__ __half g_t1[(size_t)EE * 256];     // UV node buffer fp16 (<= 50K x 512)
__device__ __half g_t2[(size_t)EE * 256];     // edge intermediate t2 (fp16, permuted)
__device__ float g_hA[(size_t)NN * 256];
__device__ float g_hB[(size_t)NN * 256];
__device__ float g_stats[1024];
__device__ float g_norm[1024];
__device__ float g_bias2[512];
__device__ int   g_deg[NN];
__device__ int   g_rowptr[NN + 1];
__device__ int   g_cursor[NN];
__device__ int   g_psrc[EE];
__device__ int   g_pdst[EE];
__device__ int   g_cnt[GG];
__device__ int   g_gstart[GG + 1];
__device__ float g_pool[GG * 256];
__device__ float g_zbuf[GG * 128];
__device__ __nv_bfloat16 g_wth[172032];
__device__ __nv_bfloat16 g_wtl[172032];

// ---------------- mma.sync / ldmatrix helpers ------------------------------
#define MMA_BF16(d, a, b)                                                        \
    asm volatile("mma.sync.aligned.m16n8k16.row.col.f32.bf16.bf16.f32 "          \
                 "{%0,%1,%2,%3}, {%4,%5,%6,%7}, {%8,%9}, {%0,%1,%2,%3};"         \
                 : "+f"((d)[0]), "+f"((d)[1]), "+f"((d)[2]), "+f"((d)[3])        \
                 : "r"((a)[0]), "r"((a)[1]), "r"((a)[2]), "r"((a)[3]),           \
                   "r"((b)[0]), "r"((b)[1]))

#define LDSM_X4(r0, r1, r2, r3, addr)                                            \
    asm volatile("ldmatrix.sync.aligned.m8n8.x4.shared.b16 {%0,%1,%2,%3}, [%4];" \
                 : "=r"(r0), "=r"(r1), "=r"(r2), "=r"(r3) : "r"(addr))

__device__ __forceinline__ uint32_t smem_u32(const void* p) {
    uint32_t a;
    asm("{ .reg .u64 t; cvta.to.shared.u64 t, %1; cvt.u32.u64 %0, t; }" : "=r"(a) : "l"(p));
    return a;
}

// ---------------- small utility kernels ----------------
__global__ void hist_deg_kernel(const int* __restrict__ dst, int* __restrict__ deg, int E) {
    int e = blockIdx.x * blockDim.x + threadIdx.x;
    if (e < E) atomicAdd(&deg[dst[e]], 1);
}
__global__ void hist_cnt_kernel(const int* __restrict__ batch, int* __restrict__ cnt, int n) {
    int i = blockIdx.x * blockDim.x + threadIdx.x;
    if (i < n) atomicAdd(&cnt[batch[i]], 1);
}
__global__ void scan_kernel(const int* __restrict__ deg, int* __restrict__ rowptr,
                            int* __restrict__ cursor, const int* __restrict__ cnt,
                            int* __restrict__ gstart, int n) {
    __shared__ int sh[1024];
    __shared__ int carry;
    int t = threadIdx.x;
    if (t == 0) carry = 0;
    __syncthreads();
    for (int base = 0; base < n; base += 1024) {
        int idx = base + t;
        int v = (idx < n) ? deg[idx] : 0;
        sh[t] = v;
        __syncthreads();
        for (int off = 1; off < 1024; off <<= 1) {
            int add = (t >= off) ? sh[t - off] : 0;
            __syncthreads();
            sh[t] += add;
            __syncthreads();
        }
        int ex = sh[t] - v;
        int cbase = carry;
        if (idx < n) { rowptr[idx] = cbase + ex; cursor[idx] = cbase + ex; }
        __syncthreads();
        if (t == 1023) carry = cbase + sh[1023];
        __syncthreads();
    }
    if (t == 0) {
        rowptr[n] = carry;
        int s = 0;
        for (int g = 0; g < GG; g++) { gstart[g] = s; s += cnt[g]; }
        gstart[GG] = s;
    }
}
__global__ void fill_csr_kernel(const int* __restrict__ src, const int* __restrict__ dst,
                                int* __restrict__ cursor,
                                int* __restrict__ psrc, int* __restrict__ pdst, int E) {
    int e = blockIdx.x * blockDim.x + threadIdx.x;
    if (e < E) {
        int d = dst[e];
        int p = atomicAdd(&cursor[d], 1);
        psrc[p] = src[e];
        pdst[p] = d;
    }
}

__global__ void convert_w_kernel(const float* __restrict__ W,
                                 __nv_bfloat16* __restrict__ Wth,
                                 __nv_bfloat16* __restrict__ Wtl,
                                 int K, int OC, int KPAD) {
    int idx = blockIdx.x * blockDim.x + threadIdx.x;
    if (idx >= OC * KPAD) return;
    int n = idx / KPAD, k = idx % KPAD;
    float w = (k < K) ? W[(size_t)k * OC + n] : 0.f;
    __nv_bfloat16 h = __float2bfloat16_rn(w);
    Wth[idx] = h;
    Wtl[idx] = __float2bfloat16_rn(w - __bfloat162float(h));
}

__global__ void convert_wsplit_kernel(const float* __restrict__ W1,
                                      __nv_bfloat16* __restrict__ Wth,
                                      __nv_bfloat16* __restrict__ Wtl,
                                      int C, int OC, int KPAD) {
    int idx = blockIdx.x * blockDim.x + threadIdx.x;
    if (idx >= 2 * OC * KPAD) return;
    int n = idx / KPAD, k = idx % KPAD;
    float w = 0.f;
    if (k < C) {
        if (n < OC) w = W1[(size_t)k * OC + n] - W1[(size_t)(k + C) * OC + n];
        else        w = W1[(size_t)(k + C) * OC + (n - OC)];
    }
    __nv_bfloat16 h = __float2bfloat16_rn(w);
    Wth[idx] = h;
    Wtl[idx] = __float2bfloat16_rn(w - __bfloat162float(h));
}

// ---------------- tensor-core GEMM (double-buffered, 1 sync/chunk) ---------
// Block tile BM x BN; warps = (BM/32) x (BN/32); warp tile 32x32 (acc 32 regs).
// 3 MMAs per k16 (hi/lo split).  Dynamic smem.  ALL outputs fp16.
// MODE 0: node GEMM, A row i = fA(f32)[i*K..].  Rows = N.
// MODE 1: edge GEMM over permuted edges; U/V fp16 gathered as WIDE raw
//         vectors (uint4/uint2), converted during store phase (overlaps MMA).
//         A row p = relu((U[pdst]+V[psrc])*an+cn); exact fp32 stats.
template <int K, int OC, int BM, int BN, int MODE, bool STATS>
__global__ __launch_bounds__(BM * BN / 32, 512 * 32 / (BM * BN))
void mgemm_kernel(const void* __restrict__ fA_v,
                  const int* __restrict__ src, const int* __restrict__ dst,
                  const float* __restrict__ an, const float* __restrict__ cn,
                  const __nv_bfloat16* __restrict__ Wth,
                  const __nv_bfloat16* __restrict__ Wtl,
                  const float* __restrict__ bias,
                  __half* __restrict__ out,
                  float* __restrict__ stat_sum, float* __restrict__ stat_sq,
                  int Rows) {
    constexpr int THREADS = BM * BN / 32;
    constexpr int MW = BM / 32;
    constexpr int KPAD = (K + 31) / 32 * 32;
    constexpr int NCH = KPAD / 32;
    constexpr int SAS = 40;
    constexpr int ASTR = (MODE == 1) ? 2 * K : K;
    constexpr int TPR = THREADS / BM;
    constexpr int UNITS = 8 / TPR;           // groups of 4 k-values per thread
    constexpr int NB_LD = 128 / BM;
    constexpr int EST = BN + 8;
    constexpr int NPASS = BM / 64;

    constexpr int ABUF = BM * SAS * 2;
    constexpr int BBUF = BN * SAS * 2;
    constexpr int OFF_AH = 0;
    constexpr int OFF_AL = 2 * ABUF;
    constexpr int OFF_BH = 4 * ABUF;
    constexpr int OFF_BL = 4 * ABUF + 2 * BBUF;
    constexpr int OFF_DST = 4 * ABUF + 4 * BBUF;
    constexpr int OFF_SRC = OFF_DST + 512;
    constexpr int OFF_AN = OFF_SRC + 512;
    constexpr int OFF_CN = OFF_AN + KPAD * 4;
    constexpr int OFF_SSUM = 64 * EST * 4;
    constexpr int OFF_SSQ = OFF_SSUM + BN * 4;

    extern __shared__ char SM[];
    int* sdst = reinterpret_cast<int*>(SM + OFF_DST);
    int* ssrc = reinterpret_cast<int*>(SM + OFF_SRC);
    float* sAn = reinterpret_cast<float*>(SM + OFF_AN);
    float* sCn = reinterpret_cast<float*>(SM + OFF_CN);

    const int tid = threadIdx.x;
    const int lane = tid & 31;
    const int wid = tid >> 5;
    const int wm = wid % MW;
    const int wn = wid / MW;
    const int e0 = blockIdx.x * BM;
    const int col0 = blockIdx.y * BN;

    const uint32_t sAh_u = smem_u32(SM + OFF_AH);
    const uint32_t sAl_u = smem_u32(SM + OFF_AL);
    const uint32_t sBh_u = smem_u32(SM + OFF_BH);
    const uint32_t sBl_u = smem_u32(SM + OFF_BL);

    if (MODE == 1) {
        if (tid < BM) {
            int e = e0 + tid;
            int ee = (e < Rows) ? e : (Rows - 1);
            sdst[tid] = dst[ee];
            ssrc[tid] = src[ee];
        }
        for (int i = tid; i < K; i += THREADS) { sAn[i] = an[i]; sCn[i] = cn[i]; }
    }
    __syncthreads();

    float acc[2][4][4];
#pragma unroll
    for (int mt = 0; mt < 2; mt++)
#pragma unroll
        for (int nt = 0; nt < 4; nt++)
#pragma unroll
            for (int j = 0; j < 4; j++) acc[mt][nt][j] = 0.f;

    const int arow = tid / TPR;
    const int acg = (tid % TPR) * (32 / TPR);
    int nd = 0, ns = 0;
    if (MODE == 1) { nd = sdst[arow]; ns = ssrc[arow]; }

    const int bn0 = tid >> 2;
    const int bu_ = tid & 3;

    float4 P[UNITS];                       // MODE 0 staging (fp32)
    uint32_t URr[UNITS * 2], VRr[UNITS * 2];  // MODE 1 staging (packed half2)
    uint4 BHr[NB_LD], BLr[NB_LD];

    auto load_chunk = [&](int ch) {
        const int k0 = ch * 32 + acg;
        if (MODE == 1) {
            // wide raw gathers: UNITS*4 halves contiguous = UNITS*8 bytes
            const __half* UVh = reinterpret_cast<const __half*>(fA_v);
            const char* Up = reinterpret_cast<const char*>(UVh + (size_t)nd * ASTR + k0);
            const char* Vp = reinterpret_cast<const char*>(UVh + (size_t)ns * ASTR + K + k0);
            if (UNITS == 1) {
                uint2 a = *reinterpret_cast<const uint2*>(Up);
                URr[0] = a.x; URr[1] = a.y;
                uint2 b = *reinterpret_cast<const uint2*>(Vp);
                VRr[0] = b.x; VRr[1] = b.y;
            } else {
#pragma unroll
                for (int u = 0; u < UNITS / 2; u++) {
                    uint4 a = *reinterpret_cast<const uint4*>(Up + u * 16);
                    URr[u * 4 + 0] = a.x; URr[u * 4 + 1] = a.y;
                    URr[u * 4 + 2] = a.z; URr[u * 4 + 3] = a.w;
                    uint4 b = *reinterpret_cast<const uint4*>(Vp + u * 16);
                    VRr[u * 4 + 0] = b.x; VRr[u * 4 + 1] = b.y;
                    VRr[u * 4 + 2] = b.z; VRr[u * 4 + 3] = b.w;
                }
            }
        } else {
            const float* fA = reinterpret_cast<const float*>(fA_v);
            const int i = e0 + arow;
            if (K % 4 == 0) {
                if (i < Rows) {
#pragma unroll
                    for (int u = 0; u < UNITS; u++)
                        P[u] = *reinterpret_cast<const float4*>(&fA[(size_t)i * K + k0 + u * 4]);
                } else {
#pragma unroll
                    for (int u = 0; u < UNITS; u++) P[u] = make_float4(0.f, 0.f, 0.f, 0.f);
                }
            } else {  // K=7 scalar path (NCH==1)
#pragma unroll
                for (int u = 0; u < UNITS; u++) {
                    float t[4];
#pragma unroll
                    for (int j = 0; j < 4; j++) {
                        int kk = k0 + u * 4 + j;
                        t[j] = (i < Rows && kk < K) ? fA[(size_t)i * K + kk] : 0.f;
                    }
                    P[u] = make_float4(t[0], t[1], t[2], t[3]);
                }
            }
        }
    };
    auto load_B = [&](int ch) {
#pragma unroll
        for (int l = 0; l < NB_LD; l++) {
            int r = bn0 + l * (THREADS / 4);
            size_t soff = (size_t)(col0 + r) * KPAD + ch * 32 + bu_ * 8;
            BHr[l] = *reinterpret_cast<const uint4*>(Wth + soff);
            BLr[l] = *reinterpret_cast<const uint4*>(Wtl + soff);
        }
    };
    auto store_chunk = [&](int ch, int buf) {
        char* aH = SM + OFF_AH + buf * ABUF;
        char* aL = SM + OFF_AL + buf * ABUF;
        const int k0 = ch * 32 + acg;
#pragma unroll
        for (int u = 0; u < UNITS; u++) {
            float4 v;
            if (MODE == 1) {
                const int k = k0 + u * 4;
                float2 p0 = __half22float2(*reinterpret_cast<__half2*>(&URr[u * 2]));
                float2 p1 = __half22float2(*reinterpret_cast<__half2*>(&URr[u * 2 + 1]));
                float2 q0 = __half22float2(*reinterpret_cast<__half2*>(&VRr[u * 2]));
                float2 q1 = __half22float2(*reinterpret_cast<__half2*>(&VRr[u * 2 + 1]));
                v.x = fmaxf((p0.x + q0.x) * sAn[k + 0] + sCn[k + 0], 0.f);
                v.y = fmaxf((p0.y + q0.y) * sAn[k + 1] + sCn[k + 1], 0.f);
                v.z = fmaxf((p1.x + q1.x) * sAn[k + 2] + sCn[k + 2], 0.f);
                v.w = fmaxf((p1.y + q1.y) * sAn[k + 3] + sCn[k + 3], 0.f);
            } else {
                v = P[u];
            }
            __nv_bfloat162 h01 = __float22bfloat162_rn(make_float2(v.x, v.y));
            __nv_bfloat162 h23 = __float22bfloat162_rn(make_float2(v.z, v.w));
            float2 hf01 = __bfloat1622float2(h01);
            float2 hf23 = __bfloat1622float2(h23);
            __nv_bfloat162 l01 = __float22bfloat162_rn(make_float2(v.x - hf01.x, v.y - hf01.y));
            __nv_bfloat162 l23 = __float22bfloat162_rn(make_float2(v.z - hf23.x, v.w - hf23.y));
            uint2 H, L;
            H.x = *reinterpret_cast<uint32_t*>(&h01);
            H.y = *reinterpret_cast<uint32_t*>(&h23);
            L.x = *reinterpret_cast<uint32_t*>(&l01);
            L.y = *reinterpret_cast<uint32_t*>(&l23);
            int so = (arow * SAS + acg + u * 4) * 2;
            *reinterpret_cast<uint2*>(aH + so) = H;
            *reinterpret_cast<uint2*>(aL + so) = L;
        }
#pragma unroll
        for (int l = 0; l < NB_LD; l++) {
            int r = bn0 + l * (THREADS / 4);
            int doff = (r * SAS + bu_ * 8) * 2;
            *reinterpret_cast<uint4*>(SM + OFF_BH + buf * BBUF + doff) = BHr[l];
            *reinterpret_cast<uint4*>(SM + OFF_BL + buf * BBUF + doff) = BLr[l];
        }
    };

    const int a_lrow = (lane & 7) + ((lane >> 3) & 1) * 8;
    const int a_lcol = (lane >> 4) * 8;
    const int b_lrow = (lane & 7) + (lane >> 4) * 8;
    const int b_lcol = ((lane >> 3) & 1) * 8;

    load_chunk(0);
    load_B(0);
    store_chunk(0, 0);
    __syncthreads();

    for (int ch = 0; ch < NCH; ch++) {
        const int cur = ch & 1;
        if (ch + 1 < NCH) { load_chunk(ch + 1); load_B(ch + 1); }

        const uint32_t aHb = sAh_u + cur * ABUF;
        const uint32_t aLb = sAl_u + cur * ABUF;
        const uint32_t bHb = sBh_u + cur * BBUF;
        const uint32_t bLb = sBl_u + cur * BBUF;
#pragma unroll
        for (int ks = 0; ks < 2; ks++) {
            const int kb = ks * 16;
            uint32_t ah[2][4], al[2][4];
#pragma unroll
            for (int mt = 0; mt < 2; mt++) {
                int r = wm * 32 + mt * 16 + a_lrow;
                uint32_t off = (uint32_t)(r * SAS + kb + a_lcol) * 2;
                LDSM_X4(ah[mt][0], ah[mt][1], ah[mt][2], ah[mt][3], aHb + off);
                LDSM_X4(al[mt][0], al[mt][1], al[mt][2], al[mt][3], aLb + off);
            }
#pragma unroll
            for (int p = 0; p < 2; p++) {
                int n0 = wn * 32 + p * 16;
                uint32_t boff = (uint32_t)((n0 + b_lrow) * SAS + kb + b_lcol) * 2;
                uint32_t bh[4], bl[4];
                LDSM_X4(bh[0], bh[1], bh[2], bh[3], bHb + boff);
                LDSM_X4(bl[0], bl[1], bl[2], bl[3], bLb + boff);
#pragma unroll
                for (int mt = 0; mt < 2; mt++) {
                    MMA_BF16(acc[mt][2 * p], ah[mt], (&bh[0]));
                    MMA_BF16(acc[mt][2 * p], ah[mt], (&bl[0]));
                    MMA_BF16(acc[mt][2 * p], al[mt], (&bh[0]));
                    MMA_BF16(acc[mt][2 * p + 1], ah[mt], (&bh[2]));
                    MMA_BF16(acc[mt][2 * p + 1], ah[mt], (&bl[2]));
                    MMA_BF16(acc[mt][2 * p + 1], al[mt], (&bh[2]));
                }
            }
        }
        if (ch + 1 < NCH) store_chunk(ch + 1, 1 - cur);
        __syncthreads();
    }

    // ---- epilogue ----
    float* ssum = reinterpret_cast<float*>(SM + OFF_SSUM);
    float* ssq = reinterpret_cast<float*>(SM + OFF_SSQ);

    const int q = lane >> 2, s = lane & 3;

#pragma unroll
    for (int nt = 0; nt < 4; nt++) {
        const int col = col0 + wn * 32 + nt * 8 + s * 2;
        const float b0 = bias[col], b1 = bias[col + 1];
#pragma unroll
        for (int mt = 0; mt < 2; mt++) {
            acc[mt][nt][0] += b0; acc[mt][nt][1] += b1;
            acc[mt][nt][2] += b0; acc[mt][nt][3] += b1;
        }
    }

    if (STATS) {   // exact fp32 stats from accumulators (before fp16 rounding)
        for (int i = tid; i < 2 * BN; i += THREADS)
            reinterpret_cast<float*>(SM + OFF_SSUM)[i] = 0.f;
        __syncthreads();
#pragma unroll
        for (int nt = 0; nt < 4; nt++) {
            const int colw = wn * 32 + nt * 8 + s * 2;
            float s0 = 0.f, q0 = 0.f, s1 = 0.f, q1 = 0.f;
#pragma unroll
            for (int mt = 0; mt < 2; mt++) {
                const int r = wm * 32 + mt * 16 + q;
                if (e0 + r < Rows) {
                    s0 += acc[mt][nt][0]; q0 += acc[mt][nt][0] * acc[mt][nt][0];
                    s1 += acc[mt][nt][1]; q1 += acc[mt][nt][1] * acc[mt][nt][1];
                }
                if (e0 + r + 8 < Rows) {
                    s0 += acc[mt][nt][2]; q0 += acc[mt][nt][2] * acc[mt][nt][2];
                    s1 += acc[mt][nt][3]; q1 += acc[mt][nt][3] * acc[mt][nt][3];
                }
            }
#pragma unroll
            for (int m = 4; m <= 16; m <<= 1) {
                s0 += __shfl_xor_sync(0xffffffff, s0, m);
                q0 += __shfl_xor_sync(0xffffffff, q0, m);
                s1 += __shfl_xor_sync(0xffffffff, s1, m);
                q1 += __shfl_xor_sync(0xffffffff, q1, m);
            }
            if (q == 0) {
                atomicAdd(&ssum[colw], s0);
                atomicAdd(&ssq[colw], q0);
                atomicAdd(&ssum[colw + 1], s1);
                atomicAdd(&ssq[colw + 1], q1);
            }
        }
        __syncthreads();
        if (tid < BN) {
            atomicAdd(&stat_sum[col0 + tid], ssum[tid]);
            atomicAdd(&stat_sq[col0 + tid], ssq[tid]);
        }
    }

    // coalesced smem-staged fp16 store (NPASS 64-row passes)
    {
        __half* ebuf = reinterpret_cast<__half*>(SM);
#pragma unroll
        for (int pass = 0; pass < NPASS; pass++) {
            __syncthreads();
            if (NPASS == 1 || (wm >> 1) == pass) {
                const int wml = wm & 1;
#pragma unroll
                for (int mt = 0; mt < 2; mt++) {
                    const int rl = wml * 32 + mt * 16 + q;
#pragma unroll
                    for (int nt = 0; nt < 4; nt++) {
                        const int colw = wn * 32 + nt * 8 + s * 2;
                        __half2 v01 = __float22half2_rn(
                            make_float2(acc[mt][nt][0], acc[mt][nt][1]));
                        __half2 v23 = __float22half2_rn(
                            make_float2(acc[mt][nt][2], acc[mt][nt][3]));
                        *reinterpret_cast<__half2*>(&ebuf[rl * EST + colw]) = v01;
                        *reinterpret_cast<__half2*>(&ebuf[(rl + 8) * EST + colw]) = v23;
                    }
                }
            }
            __syncthreads();
            constexpr int II = 8 * BN / THREADS;
#pragma unroll
            for (int ii = 0; ii < II; ii++) {
                const int i = tid + ii * THREADS;
                const int row = i / (BN / 8), c8 = i % (BN / 8);
                const int e = e0 + pass * 64 + row;
                if (e < Rows) {
                    uint4 v = *reinterpret_cast<uint4*>(&ebuf[row * EST + c8 * 8]);
                    *reinterpret_cast<uint4*>(&out[(size_t)e * OC + col0 + c8 * 8]) = v;
                }
            }
        }
    }
}

// ---------------- node-centric edge stats (fp16 UV, wide loads) ------------
template <int OC>
__global__ __launch_bounds__(256)
void estats_kernel(const __half* __restrict__ UV, const int* __restrict__ psrc,
                   const int* __restrict__ rowptr,
                   float* __restrict__ sum, float* __restrict__ sq, int n) {
    constexpr int R = OC / 64;           // half2 pairs per lane
    __shared__ float ss[OC], sv[OC];
    const int tid = threadIdx.x, lane = tid & 31, wid = tid >> 5;
    for (int i = tid; i < OC; i += 256) { ss[i] = 0.f; sv[i] = 0.f; }
    __syncthreads();
    float2 s[R], q[R];
#pragma unroll
    for (int j = 0; j < R; j++) { s[j] = make_float2(0.f, 0.f); q[j] = make_float2(0.f, 0.f); }
    const int nwarps = gridDim.x * 8;
    for (int i = blockIdx.x * 8 + wid; i < n; i += nwarps) {
        const int beg = rowptr[i], end = rowptr[i + 1];
        const float dg = (float)(end - beg);
        float2 U[R], sV[R], sV2[R];
        const __half2* Ur = reinterpret_cast<const __half2*>(UV + (size_t)i * (2 * OC));
#pragma unroll
        for (int j = 0; j < R; j++) {
            U[j] = __half22float2(Ur[j * 32 + lane]);
            sV[j] = make_float2(0.f, 0.f);
            sV2[j] = make_float2(0.f, 0.f);
        }
        for (int p = beg; p < end; p++) {
            const __half2* Vr = reinterpret_cast<const __half2*>(
                UV + (size_t)psrc[p] * (2 * OC) + OC);
#pragma unroll
            for (int j = 0; j < R; j++) {
                float2 v = __half22float2(Vr[j * 32 + lane]);
                sV[j].x += v.x; sV[j].y += v.y;
                sV2[j].x += v.x * v.x; sV2[j].y += v.y * v.y;
            }
        }
#pragma unroll
        for (int j = 0; j < R; j++) {
            s[j].x += dg * U[j].x + sV[j].x;
            s[j].y += dg * U[j].y + sV[j].y;
            q[j].x += dg * U[j].x * U[j].x + 2.f * U[j].x * sV[j].x + sV2[j].x;
            q[j].y += dg * U[j].y * U[j].y + 2.f * U[j].y * sV[j].y + sV2[j].y;
        }
    }
#pragma unroll
    for (int j = 0; j < R; j++) {
        int ch = j * 64 + lane * 2;
        atomicAdd(&ss[ch], s[j].x);
        atomicAdd(&ss[ch + 1], s[j].y);
        atomicAdd(&sv[ch], q[j].x);
        atomicAdd(&sv[ch + 1], q[j].y);
    }
    __syncthreads();
    for (int i = tid; i < OC; i += 256) {
        atomicAdd(&sum[i], ss[i]);
        atomicAdd(&sq[i], sv[i]);
    }
}

// ---------------- BN finalize (self-zeroing) ----------------
__global__ void finalize_kernel(float* __restrict__ sum, float* __restrict__ sq,
                                const float* __restrict__ gamma, const float* __restrict__ beta,
                                float* __restrict__ a, float* __restrict__ c,
                                int OC, float invE) {
    int i = blockIdx.x * blockDim.x + threadIdx.x;
    if (i < OC) {
        float m = sum[i] * invE;
        float var = sq[i] * invE - m * m;
        float rs = rsqrtf(var + 1e-5f);
        float ai = gamma[i] * rs;
        a[i] = ai;
        c[i] = beta[i] - m * ai;
        sum[i] = 0.f;
        sq[i] = 0.f;
    }
}

// ---------------- normalize + relu + mean-aggregate (fp16 rows) ------------
template <int OC>
__global__ __launch_bounds__(256)
void aggregate_kernel(const __half* __restrict__ t, const int* __restrict__ rowptr,
                      const float* __restrict__ a,
                      const float* __restrict__ c, float* __restrict__ hout, int n) {
    int warp = (blockIdx.x * blockDim.x + threadIdx.x) >> 5;
    int lane = threadIdx.x & 31;
    if (warp >= n) return;
    constexpr int R = OC / 64;           // half2 pairs per lane
    float2 av[R], cv[R], acc[R];
#pragma unroll
    for (int j = 0; j < R; j++) {
        int ch = j * 64 + lane * 2;
        av[j] = make_float2(a[ch], a[ch + 1]);
        cv[j] = make_float2(c[ch], c[ch + 1]);
        acc[j] = make_float2(0.f, 0.f);
    }
    int beg = rowptr[warp], end = rowptr[warp + 1];
    for (int p = beg; p < end; p++) {
        const __half2* rowp =
            reinterpret_cast<const __half2*>(t + (size_t)p * OC);
#pragma unroll
        for (int j = 0; j < R; j++) {
            float2 v = __half22float2(rowp[j * 32 + lane]);
            acc[j].x += fmaxf(v.x * av[j].x + cv[j].x, 0.f);
            acc[j].y += fmaxf(v.y * av[j].y + cv[j].y, 0.f);
        }
    }
    float inv = 1.f / fmaxf((float)(end - beg), 1.f);
#pragma unroll
    for (int j = 0; j < R; j++) {
        int ch = j * 64 + lane * 2;
        hout[(size_t)warp * OC + ch] = acc[j].x * inv;
        hout[(size_t)warp * OC + ch + 1] = acc[j].y * inv;
    }
}

// ---------------- global mean pool + head ----------------
__global__ void pool_kernel(const float* __restrict__ h, const int* __restrict__ gstart,
                            float* __restrict__ pool) {
    int g = blockIdx.x;
    int ch = threadIdx.x;
    int beg = gstart[g], end = gstart[g + 1];
    float s = 0.f;
    for (int nidx = beg; nidx < end; nidx++) s += h[(size_t)nidx * 256 + ch];
    pool[g * 256 + ch] = s / fmaxf((float)(end - beg), 1.f);
}
__global__ void head1_kernel(const float* __restrict__ pool, const float* __restrict__ W,
                             const float* __restrict__ b, float* __restrict__ z) {
    int g = blockIdx.x, j = threadIdx.x;
    __shared__ float sp[256];
    sp[j] = pool[g * 256 + j];
    sp[j + 128] = pool[g * 256 + j + 128];
    __syncthreads();
    float s = b[j];
#pragma unroll 8
    for (int k = 0; k < 256; k++) s += sp[k] * W[k * 128 + j];
    z[g * 128 + j] = fmaxf(s, 0.f);
}
__global__ void head2_kernel(const float* __restrict__ z, const float* __restrict__ W,
                             const float* __restrict__ b, float* __restrict__ out) {
    int t = threadIdx.x;
    int g = t >> 1, j = t & 1;
    float s = b[j];
#pragma unroll 8
    for (int k = 0; k < 128; k++) s += z[g * 128 + k] * W[k * 2 + j];
    out[g * 2 + j] = s;
}

// ---------------- launch ----------------
static inline int gemm_smem(int KPAD, int BM, int BN) {
    int prod = 4 * BM * 80 + 4 * BN * 80 + 1024 + 2 * KPAD * 4;
    int epi = 64 * (BN + 8) * 4 + 8 * BN;
    return prod > epi ? prod : epi;
}

extern "C" void kernel_launch(void* const* d_in, const int* in_sizes, int n_in,
                              void* d_out, int out_size) {
    const float* x     = (const float*)d_in[0];
    const int*   ei    = (const int*)d_in[1];
    const int*   batch = (const int*)d_in[2];

    const int E = in_sizes[1] / 2;
    const int n = in_sizes[2];
    const int* srcp = ei;
    const int* dstp = ei + E;

    const float* W[3][2];  const float* B[3][2];
    const float* Gm[3][2]; const float* Bt[3][2];
    for (int l = 0; l < 3; l++) {
        int base = 3 + l * 8;
        W[l][0]  = (const float*)d_in[base + 0];
        B[l][0]  = (const float*)d_in[base + 1];
        Gm[l][0] = (const float*)d_in[base + 2];
        Bt[l][0] = (const float*)d_in[base + 3];
        W[l][1]  = (const float*)d_in[base + 4];
        B[l][1]  = (const float*)d_in[base + 5];
        Gm[l][1] = (const float*)d_in[base + 6];
        Bt[l][1] = (const float*)d_in[base + 7];
    }
    const float* hW1 = (const float*)d_in[27];
    const float* hb1 = (const float*)d_in[28];
    const float* hW2 = (const float*)d_in[29];
    const float* hb2 = (const float*)d_in[30];

    float *hA, *hB, *stats, *norm, *pool, *zbuf, *bias2;
    __half *UV, *t2;
    int *deg, *rowptr, *cursor, *psrc, *pdst, *cnt, *gstart;
    __nv_bfloat16 *wth, *wtl;
    cudaGetSymbolAddress((void**)&UV, g_t1);
    cudaGetSymbolAddress((void**)&t2, g_t2);
    cudaGetSymbolAddress((void**)&hA, g_hA);
    cudaGetSymbolAddress((void**)&hB, g_hB);
    cudaGetSymbolAddress((void**)&stats, g_stats);
    cudaGetSymbolAddress((void**)&norm, g_norm);
    cudaGetSymbolAddress((void**)&bias2, g_bias2);
    cudaGetSymbolAddress((void**)&deg, g_deg);
    cudaGetSymbolAddress((void**)&rowptr, g_rowptr);
    cudaGetSymbolAddress((void**)&cursor, g_cursor);
    cudaGetSymbolAddress((void**)&psrc, g_psrc);
    cudaGetSymbolAddress((void**)&pdst, g_pdst);
    cudaGetSymbolAddress((void**)&cnt, g_cnt);
    cudaGetSymbolAddress((void**)&gstart, g_gstart);
    cudaGetSymbolAddress((void**)&pool, g_pool);
    cudaGetSymbolAddress((void**)&zbuf, g_zbuf);
    cudaGetSymbolAddress((void**)&wth, g_wth);
    cudaGetSymbolAddress((void**)&wtl, g_wtl);

    float* sum1 = stats + 0;   float* sq1 = stats + 256;
    float* sum2 = stats + 512; float* sq2 = stats + 768;
    float* a1 = norm + 0;   float* c1 = norm + 256;
    float* a2 = norm + 512; float* c2 = norm + 768;

    const float invE = 1.f / (float)E;
    const int EB128 = (E + 127) / 128;
    const int EB64 = (E + 63) / 64;
    const int NB = (n + 127) / 128;
    const int EG = (E + 255) / 256;
    const int NG = (n + 255) / 256;
    const int AGG = (n * 32 + 255) / 256;
    const int SGRID = 592;

    cudaFuncSetAttribute(mgemm_kernel<7, 128, 128, 128, 0, false>,   cudaFuncAttributeMaxDynamicSharedMemorySize, gemm_smem(32, 128, 128));
    cudaFuncSetAttribute(mgemm_kernel<64, 64, 128, 64, 1, true>,     cudaFuncAttributeMaxDynamicSharedMemorySize, gemm_smem(64, 128, 64));
    cudaFuncSetAttribute(mgemm_kernel<64, 256, 128, 128, 0, false>,  cudaFuncAttributeMaxDynamicSharedMemorySize, gemm_smem(64, 128, 128));
    cudaFuncSetAttribute(mgemm_kernel<128, 128, 128, 128, 1, true>,  cudaFuncAttributeMaxDynamicSharedMemorySize, gemm_smem(128, 128, 128));
    cudaFuncSetAttribute(mgemm_kernel<128, 512, 128, 128, 0, false>, cudaFuncAttributeMaxDynamicSharedMemorySize, gemm_smem(128, 128, 128));
    cudaFuncSetAttribute(mgemm_kernel<256, 256, 64, 256, 1, true>,   cudaFuncAttributeMaxDynamicSharedMemorySize, gemm_smem(256, 64, 256));

    // ---- CSR build (permuted src/dst directly) ----
    cudaMemsetAsync(deg, 0, n * sizeof(int));
    cudaMemsetAsync(cnt, 0, GG * sizeof(int));
    cudaMemsetAsync(stats, 0, 1024 * sizeof(float));
    hist_deg_kernel<<<EG, 256>>>(dstp, deg, E);
    hist_cnt_kernel<<<NG, 256>>>(batch, cnt, n);
    scan_kernel<<<1, 1024>>>(deg, rowptr, cursor, cnt, gstart, n);
    fill_csr_kernel<<<EG, 256>>>(srcp, dstp, cursor, psrc, pdst, E);

    // ---- weight conversion ----
    convert_wsplit_kernel<<<(128 * 32 + 255) / 256, 256>>>(W[0][0], wth + 0, wtl + 0, 7, 64, 32);
    convert_w_kernel<<<(64 * 64 + 255) / 256, 256>>>(W[0][1], wth + 4096, wtl + 4096, 64, 64, 64);
    convert_wsplit_kernel<<<(256 * 64 + 255) / 256, 256>>>(W[1][0], wth + 8192, wtl + 8192, 64, 128, 64);
    convert_w_kernel<<<(128 * 128 + 255) / 256, 256>>>(W[1][1], wth + 24576, wtl + 24576, 128, 128, 128);
    convert_wsplit_kernel<<<(512 * 128 + 255) / 256, 256>>>(W[2][0], wth + 40960, wtl + 40960, 128, 256, 128);
    convert_w_kernel<<<(256 * 256 + 255) / 256, 256>>>(W[2][1], wth + 106496, wtl + 106496, 256, 256, 256);

    // ==== layer 1: 7 -> 64 ====
    cudaMemsetAsync(bias2, 0, 512 * sizeof(float));
    cudaMemcpyAsync(bias2, B[0][0], 64 * sizeof(float), cudaMemcpyDeviceToDevice);
    mgemm_kernel<7, 128, 128, 128, 0, false><<<dim3(NB, 1), 512, gemm_smem(32, 128, 128)>>>(
        x, nullptr, nullptr, nullptr, nullptr, wth + 0, wtl + 0, bias2, UV, nullptr, nullptr, n);
    estats_kernel<64><<<SGRID, 256>>>(UV, psrc, rowptr, sum1, sq1, n);
    finalize_kernel<<<1, 64>>>(sum1, sq1, Gm[0][0], Bt[0][0], a1, c1, 64, invE);
    mgemm_kernel<64, 64, 128, 64, 1, true><<<dim3(EB128, 1), 256, gemm_smem(64, 128, 64)>>>(
        UV, psrc, pdst, a1, c1, wth + 4096, wtl + 4096, B[0][1], t2, sum2, sq2, E);
    finalize_kernel<<<1, 64>>>(sum2, sq2, Gm[0][1], Bt[0][1], a2, c2, 64, invE);
    aggregate_kernel<64><<<AGG, 256>>>(t2, rowptr, a2, c2, hA, n);

    // ==== layer 2: 64 -> 128 ====
    cudaMemsetAsync(bias2, 0, 512 * sizeof(float));
    cudaMemcpyAsync(bias2, B[1][0], 128 * sizeof(float), cudaMemcpyDeviceToDevice);
    mgemm_kernel<64, 256, 128, 128, 0, false><<<dim3(NB, 2), 512, gemm_smem(64, 128, 128)>>>(
        hA, nullptr, nullptr, nullptr, nullptr, wth + 8192, wtl + 8192, bias2, UV, nullptr, nullptr, n);
    estats_kernel<128><<<SGRID, 256>>>(UV, psrc, rowptr, sum1, sq1, n);
    finalize_kernel<<<1, 128>>>(sum1, sq1, Gm[1][0], Bt[1][0], a1, c1, 128, invE);
    mgemm_kernel<128, 128, 128, 128, 1, true><<<dim3(EB128, 1), 512, gemm_smem(128, 128, 128)>>>(
        UV, psrc, pdst, a1, c1, wth + 24576, wtl + 24576, B[1][1], t2, sum2, sq2, E);
    finalize_kernel<<<1, 128>>>(sum2, sq2, Gm[1][1], Bt[1][1], a2, c2, 128, invE);
    aggregate_kernel<128><<<AGG, 256>>>(t2, rowptr, a2, c2, hB, n);

    // ==== layer 3: 128 -> 256 ====
    cudaMemsetAsync(bias2, 0, 512 * sizeof(float));
    cudaMemcpyAsync(bias2, B[2][0], 256 * sizeof(float), cudaMemcpyDeviceToDevice);
    mgemm_kernel<128, 512, 128, 128, 0, false><<<dim3(NB, 4), 512, gemm_smem(128, 128, 128)>>>(
        hB, nullptr, nullptr, nullptr, nullptr, wth + 40960, wtl + 40960, bias2, UV, nullptr, nullptr, n);
    estats_kernel<256><<<SGRID, 256>>>(UV, psrc, rowptr, sum1, sq1, n);
    finalize_kernel<<<1, 256>>>(sum1, sq1, Gm[2][0], Bt[2][0], a1, c1, 256, invE);
    mgemm_kernel<256, 256, 64, 256, 1, true><<<dim3(EB64, 1), 512, gemm_smem(256, 64, 256)>>>(
        UV, psrc, pdst, a1, c1, wth + 106496, wtl + 106496, B[2][1], t2, sum2, sq2, E);
    finalize_kernel<<<1, 256>>>(sum2, sq2, Gm[2][1], Bt[2][1], a2, c2, 256, invE);
    aggregate_kernel<256><<<AGG, 256>>>(t2, rowptr, a2, c2, hA, n);

    // ---- pool + head ----
    pool_kernel<<<GG, 256>>>(hA, gstart, pool);
    head1_kernel<<<GG, 128>>>(pool, hW1, hb1, zbuf);
    head2_kernel<<<1, 128>>>(zbuf, hW2, hb2, (float*)d_out);
}